// round 12
// baseline (speedup 1.0000x reference)
#include <cuda_runtime.h>
#include <math.h>

#define NN 768
#define CS 384
#define CZ 128
#define CH 16
#define HH 12
#define PQ 4
#define PV 8
#define HC (HH*CH)          /* 192 */
#define RAW_TOT 1152        /* 192 q + 384 kv + 144 qp + 432 kvp */

typedef unsigned long long u64;

__device__ __forceinline__ u64 pk2(float x, float y){
    u64 r; asm("mov.b64 %0, {%1,%2};" : "=l"(r) : "f"(x), "f"(y)); return r;
}
__device__ __forceinline__ void fma2(u64 &d, u64 a, u64 b){
    asm("fma.rn.f32x2 %0, %1, %2, %0;" : "+l"(d) : "l"(a), "l"(b));
}
__device__ __forceinline__ void upk2(float &x, float &y, u64 v){
    asm("mov.b64 {%0,%1}, %2;" : "=f"(x), "=f"(y) : "l"(v));
}

/* ---------------- scratch (device globals, no allocs) ---------------- */
__device__ float g_q   [NN*HC];
__device__ float g_kT  [(HH*28)*NN];        /* [h*28+u][j]: u<16 k chan, u>=16 kpt p*3+c */
__device__ float g_vT  [(HH*40)*NN];        /* [h*40+u][j]: u<16 v chan, u>=16 vpt p*3+c */
__device__ float g_qpts[NN*48*3];
__device__ float g_A   [(size_t)HH*NN*NN];  /* logits -> attn, [h][i][j] */
__device__ float g_pzT [(size_t)NN*32*NN];  /* [i][d][j] */
__device__ float g_o   [NN*HC];
__device__ float g_opt [NN*96*3];           /* global-frame o_pt, [i][h*8+p][3] */
__device__ float g_opair[NN*HH*32];
__device__ float g_feats[(size_t)NN*960];

/* ---------------- K1: input projections (8 residues per block) ---------------- */
#define K1_IT 8
#define K1_SMEM ((K1_IT*CS + K1_IT*RAW_TOT)*4)

__global__ __launch_bounds__(256) void k1_proj(
    const float* __restrict__ s, const float* __restrict__ rot, const float* __restrict__ trans,
    const float* __restrict__ Wq, const float* __restrict__ bq,
    const float* __restrict__ Wkv, const float* __restrict__ bkv,
    const float* __restrict__ Wqp, const float* __restrict__ bqp,
    const float* __restrict__ Wkvp, const float* __restrict__ bkvp)
{
    extern __shared__ float sm1[];
    float* s_s = sm1;                 /* [K1_IT][384] */
    float* raw = sm1 + K1_IT*CS;      /* [K1_IT][1152] */
    const int i0 = blockIdx.x * K1_IT;
    const int tid = threadIdx.x;

    for (int l = tid; l < K1_IT*CS; l += 256) {
        int ii = l / CS, c = l % CS;
        s_s[ii*CS + c] = s[(size_t)(i0+ii)*CS + c];
    }
    __syncthreads();

    const int w = tid >> 5, lane = tid & 31;
    for (int o = w; o < RAW_TOT; o += 8) {
        const float* wrow; float bias;
        if (o < 192)      { wrow = Wq   + (size_t)o*CS;        bias = bq[o]; }
        else if (o < 576) { wrow = Wkv  + (size_t)(o-192)*CS;  bias = bkv[o-192]; }
        else if (o < 720) { wrow = Wqp  + (size_t)(o-576)*CS;  bias = bqp[o-576]; }
        else              { wrow = Wkvp + (size_t)(o-720)*CS;  bias = bkvp[o-720]; }
        const float4* wr4 = (const float4*)wrow;
        float acc[K1_IT];
        #pragma unroll
        for (int ii = 0; ii < K1_IT; ii++) acc[ii] = 0.f;
        for (int cc = lane; cc < CS/4; cc += 32) {
            float4 wv = wr4[cc];
            #pragma unroll
            for (int ii = 0; ii < K1_IT; ii++) {
                float4 sv = *(const float4*)(s_s + ii*CS + cc*4);
                acc[ii] += sv.x*wv.x + sv.y*wv.y + sv.z*wv.z + sv.w*wv.w;
            }
        }
        #pragma unroll
        for (int ii = 0; ii < K1_IT; ii++) {
            float v = acc[ii];
            #pragma unroll
            for (int off = 16; off > 0; off >>= 1) v += __shfl_xor_sync(~0u, v, off);
            if (lane == 0) raw[ii*RAW_TOT + o] = v + bias;
        }
    }
    __syncthreads();

    /* scatter + rigid transforms */
    for (int l = tid; l < K1_IT*768; l += 256) {
        int ii = l / 768, u = l % 768;
        int i = i0 + ii;
        const float* rw = raw + ii*RAW_TOT;
        if (u < 192) {
            g_q[i*HC + u] = rw[u];
        } else if (u < 576) {
            int o = u - 192; int h = o >> 5; int cc = o & 31;
            float v = rw[192 + o];
            if (cc < 16) g_kT[(size_t)(h*28 + cc)*NN + i] = v;
            else         g_vT[(size_t)(h*40 + (cc-16))*NN + i] = v;
        } else {
            float R0=rot[i*9+0],R1=rot[i*9+1],R2=rot[i*9+2],
                  R3=rot[i*9+3],R4=rot[i*9+4],R5=rot[i*9+5],
                  R6=rot[i*9+6],R7=rot[i*9+7],R8=rot[i*9+8];
            float T0=trans[i*3+0],T1=trans[i*3+1],T2=trans[i*3+2];
            if (u < 624) {
                int p = u - 576;   /* 0..47 q points */
                float x = rw[576+p], y = rw[576+48+p], z = rw[576+96+p];
                float ox = R0*x + R1*y + R2*z + T0;
                float oy = R3*x + R4*y + R5*z + T1;
                float oz = R6*x + R7*y + R8*z + T2;
                int base = (i*48 + p)*3;
                g_qpts[base+0] = ox; g_qpts[base+1] = oy; g_qpts[base+2] = oz;
            } else {
                int p = u - 624;   /* 0..143 kv points */
                float x = rw[720+p], y = rw[720+144+p], z = rw[720+288+p];
                float ox = R0*x + R1*y + R2*z + T0;
                float oy = R3*x + R4*y + R5*z + T1;
                float oz = R6*x + R7*y + R8*z + T2;
                int h = p / 12, t2 = p % 12;
                if (t2 < 4) {
                    size_t b = (size_t)(h*28 + 16 + t2*3)*NN + i;
                    g_kT[b] = ox; g_kT[b+NN] = oy; g_kT[b+2*NN] = oz;
                } else {
                    int pp = t2 - 4;
                    size_t b = (size_t)(h*40 + 16 + pp*3)*NN + i;
                    g_vT[b] = ox; g_vT[b+NN] = oy; g_vT[b+2*NN] = oz;
                }
            }
        }
    }
}

/* ---------------- K2: z projection with packed f32x2 FMA ---------------- */
#define JT 128
#define ZPAD 132
#define K2_SMEM ((JT*ZPAD + 128*48)*4)   /* 92160 B */

__global__ __launch_bounds__(128) void k2_zproj(
    const float* __restrict__ z, const float* __restrict__ Wb, const float* __restrict__ bb,
    const float* __restrict__ Wdz, const float* __restrict__ bdz)
{
    extern __shared__ float sm2[];
    float* zs  = sm2;              /* [128][132] */
    float* wst = sm2 + JT*ZPAD;    /* [c:128][o:48], transposed weights */
    const int i = blockIdx.y;
    const int jbase = blockIdx.x * JT;
    const int tid = threadIdx.x;

    for (int l = tid; l < 48*CZ; l += 128) {
        int o = l >> 7, c = l & 127;
        float v = 0.f;                               /* o>=44: padding, stays zero */
        if (o < 12)      v = Wb[o*CZ + c];
        else if (o < 44) v = Wdz[(o-12)*CZ + c];
        wst[c*48 + o] = v;
    }
    const float4* zg = (const float4*)(z + ((size_t)i*NN + jbase)*CZ);
    for (int l4 = tid; l4 < JT*CZ/4; l4 += 128) {
        float4 v = zg[l4];
        int r = l4 >> 5, c4 = l4 & 31;
        *(float4*)(zs + r*ZPAD + c4*4) = v;
    }
    __syncthreads();

    const int jg = tid & 15;       /* j = jbase + jg + 16*m */
    const int og = tid >> 4;       /* o = og*6 + oo, og 0..7 */
    u64 acc[8][3];
    #pragma unroll
    for (int m = 0; m < 8; m++) { acc[m][0]=0ull; acc[m][1]=0ull; acc[m][2]=0ull; }

    for (int c4 = 0; c4 < CZ/4; c4++) {
        float4 zr[8];
        #pragma unroll
        for (int m = 0; m < 8; m++)
            zr[m] = *(const float4*)(zs + (jg + 16*m)*ZPAD + c4*4);
        #pragma unroll
        for (int cc = 0; cc < 4; cc++) {
            const float* wrow = wst + (c4*4+cc)*48 + og*6;
            u64 w0 = *(const u64*)(wrow);
            u64 w1 = *(const u64*)(wrow + 2);
            u64 w2 = *(const u64*)(wrow + 4);
            #pragma unroll
            for (int m = 0; m < 8; m++) {
                float zv = (cc==0) ? zr[m].x : (cc==1) ? zr[m].y : (cc==2) ? zr[m].z : zr[m].w;
                u64 zz = pk2(zv, zv);
                fma2(acc[m][0], zz, w0);
                fma2(acc[m][1], zz, w1);
                fma2(acc[m][2], zz, w2);
            }
        }
    }

    /* preload biases (guard o>=44: padding outputs) */
    float bs[6];
    #pragma unroll
    for (int oo = 0; oo < 6; oo++) {
        int o = og*6 + oo;
        bs[oo] = (o < 12) ? bb[o] : (o < 44) ? bdz[o-12] : 0.f;
    }
    #pragma unroll
    for (int m = 0; m < 8; m++) {
        float av[6];
        upk2(av[0], av[1], acc[m][0]);
        upk2(av[2], av[3], acc[m][1]);
        upk2(av[4], av[5], acc[m][2]);
        int j = jbase + jg + 16*m;
        #pragma unroll
        for (int oo = 0; oo < 6; oo++) {
            int o = og*6 + oo;
            float v = av[oo] + bs[oo];
            if (o < 12)      g_A[((size_t)o*NN + i)*NN + j] = v;
            else if (o < 44) g_pzT[((size_t)i*32 + (o-12))*NN + j] = v;
        }
    }
}

/* ---------------- K3: logits + softmax, 2 rows per block, coalesced kT ------- */
__global__ __launch_bounds__(256) void k3_softmax(const float* __restrict__ mask)
{
    const int i0 = blockIdx.x * 2, h = blockIdx.y;
    __shared__ float l_s[2][NN];
    __shared__ float q_s[2][16];
    __shared__ float qp_s[2][12];
    __shared__ float red[8];
    const int tid = threadIdx.x;
    if (tid < 32) q_s[tid>>4][tid&15] = g_q[(i0 + (tid>>4))*HC + h*16 + (tid&15)];
    if (tid >= 32 && tid < 56) {
        int idx = tid - 32; int r = idx / 12, u = idx % 12;
        qp_s[r][u] = g_qpts[((i0+r)*48 + h*4)*3 + u];
    }
    __syncthreads();

    const float m0 = mask[i0], m1 = mask[i0+1];
    const float c1 = 0.14433756729740643f;   /* sqrt(1/48) */
    const float c2 = 0.5773502691896258f;    /* sqrt(1/3)  */
    const float* kTb = g_kT + (size_t)h*28*NN;
    float lmax0 = -1e30f, lmax1 = -1e30f;
    for (int j = tid; j < NN; j += 256) {
        float kv[28];
        #pragma unroll
        for (int u = 0; u < 28; u++) kv[u] = kTb[(size_t)u*NN + j];
        float mj = mask[j];
        float b0 = g_A[((size_t)h*NN + i0  )*NN + j];
        float b1 = g_A[((size_t)h*NN + i0+1)*NN + j];
        float qk0 = 0.f, qk1 = 0.f;
        #pragma unroll
        for (int c = 0; c < 16; c++) { qk0 += q_s[0][c]*kv[c]; qk1 += q_s[1][c]*kv[c]; }
        float pt0 = 0.f, pt1 = 0.f;
        #pragma unroll
        for (int u = 0; u < 12; u++) {
            float d0 = qp_s[0][u] - kv[16+u]; pt0 += d0*d0;
            float d1 = qp_s[1][u] - kv[16+u]; pt1 += d1*d1;
        }
        float lg0 = c1*qk0 + c2*b0 - 0.5f*pt0 + 100000.0f*(m0*mj - 1.0f);
        float lg1 = c1*qk1 + c2*b1 - 0.5f*pt1 + 100000.0f*(m1*mj - 1.0f);
        l_s[0][j] = lg0; l_s[1][j] = lg1;
        lmax0 = fmaxf(lmax0, lg0); lmax1 = fmaxf(lmax1, lg1);
    }

    #pragma unroll
    for (int r = 0; r < 2; r++) {
        float lmax = r ? lmax1 : lmax0;
        #pragma unroll
        for (int o = 16; o > 0; o >>= 1) lmax = fmaxf(lmax, __shfl_xor_sync(~0u, lmax, o));
        if ((tid & 31) == 0) red[tid>>5] = lmax;
        __syncthreads();
        if (tid < 32) {
            float v = (tid < 8) ? red[tid] : -1e30f;
            #pragma unroll
            for (int o = 4; o > 0; o >>= 1) v = fmaxf(v, __shfl_xor_sync(~0u, v, o));
            if (tid == 0) red[0] = v;
        }
        __syncthreads();
        lmax = red[0];
        __syncthreads();

        float lsum = 0.f;
        for (int j = tid; j < NN; j += 256) {
            float e = __expf(l_s[r][j] - lmax);
            l_s[r][j] = e;
            lsum += e;
        }
        #pragma unroll
        for (int o = 16; o > 0; o >>= 1) lsum += __shfl_xor_sync(~0u, lsum, o);
        if ((tid & 31) == 0) red[tid>>5] = lsum;
        __syncthreads();
        if (tid < 32) {
            float v = (tid < 8) ? red[tid] : 0.f;
            #pragma unroll
            for (int o = 4; o > 0; o >>= 1) v += __shfl_xor_sync(~0u, v, o);
            if (tid == 0) red[0] = v;
        }
        __syncthreads();
        float inv = 1.0f / red[0];
        float* arow = g_A + ((size_t)h*NN + i0 + r)*NN;
        for (int j = tid; j < NN; j += 256) arow[j] = l_s[r][j]*inv;
        __syncthreads();
    }
}

/* ---------------- K4: weighted sums per residue, float4 + bounded regs -------- */
__global__ __launch_bounds__(256, 4) void k4_out(void)
{
    const int i = blockIdx.x;
    __shared__ float a_s[HH][NN];
    const int tid = threadIdx.x;
    for (int l = tid; l < HH*(NN/4); l += 256) {
        int h = l / (NN/4), j4 = l % (NN/4);
        ((float4*)a_s[h])[j4] = ((const float4*)(g_A + ((size_t)h*NN + i)*NN))[j4];
    }
    __syncthreads();
    const int w = tid >> 5, lane = tid & 31;

    /* part 1: o + o_pt — 120 tasks, each 4 u-rows sharing one a-load */
    for (int t = w; t < 120; t += 8) {
        int h = t / 10, u0 = (t % 10) * 4;
        const float4* a4 = (const float4*)a_s[h];
        const float4* v0 = (const float4*)(g_vT + (size_t)(h*40 + u0    )*NN);
        const float4* v1 = (const float4*)(g_vT + (size_t)(h*40 + u0 + 1)*NN);
        const float4* v2 = (const float4*)(g_vT + (size_t)(h*40 + u0 + 2)*NN);
        const float4* v3 = (const float4*)(g_vT + (size_t)(h*40 + u0 + 3)*NN);
        float ac[4] = {0.f, 0.f, 0.f, 0.f};
        #pragma unroll
        for (int jc = 0; jc < 6; jc++) {
            int idx = jc*32 + lane;
            float4 av = a4[idx];
            float4 b0 = v0[idx], b1 = v1[idx], b2 = v2[idx], b3 = v3[idx];
            ac[0] += av.x*b0.x + av.y*b0.y + av.z*b0.z + av.w*b0.w;
            ac[1] += av.x*b1.x + av.y*b1.y + av.z*b1.z + av.w*b1.w;
            ac[2] += av.x*b2.x + av.y*b2.y + av.z*b2.z + av.w*b2.w;
            ac[3] += av.x*b3.x + av.y*b3.y + av.z*b3.z + av.w*b3.w;
        }
        #pragma unroll
        for (int o = 16; o > 0; o >>= 1) {
            ac[0] += __shfl_xor_sync(~0u, ac[0], o);
            ac[1] += __shfl_xor_sync(~0u, ac[1], o);
            ac[2] += __shfl_xor_sync(~0u, ac[2], o);
            ac[3] += __shfl_xor_sync(~0u, ac[3], o);
        }
        if (lane == 0) {
            #pragma unroll
            for (int k = 0; k < 4; k++) {
                int u = u0 + k;
                if (u < 16) g_o[i*HC + h*16 + u] = ac[k];
                else { int pp = u - 16; g_opt[(i*96 + h*8 + pp/3)*3 + pp%3] = ac[k]; }
            }
        }
    }

    /* part 2: o_pair — warp owns 4 d, one at a time (12 scalar accumulators) */
    for (int dd = 0; dd < 4; dd++) {
        int d = w*4 + dd;
        const float4* pz4 = (const float4*)(g_pzT + ((size_t)i*32 + d)*NN);
        float acc[HH];
        #pragma unroll
        for (int h = 0; h < HH; h++) acc[h] = 0.f;
        #pragma unroll
        for (int jc = 0; jc < 6; jc++) {
            int idx = jc*32 + lane;
            float4 q = pz4[idx];
            #pragma unroll
            for (int h = 0; h < HH; h++) {
                float4 av = ((const float4*)a_s[h])[idx];
                acc[h] += av.x*q.x + av.y*q.y + av.z*q.z + av.w*q.w;
            }
        }
        #pragma unroll
        for (int h = 0; h < HH; h++) {
            float v = acc[h];
            #pragma unroll
            for (int o = 16; o > 0; o >>= 1) v += __shfl_xor_sync(~0u, v, o);
            if (lane == 0) g_opair[(i*HH + h)*32 + d] = v;
        }
    }
}

/* ---------------- K5a: feats assembly + l1 out ---------------- */
__global__ __launch_bounds__(128) void k5a_feats(
    const float* __restrict__ l1_feats, const float* __restrict__ rot,
    const float* __restrict__ trans, const float* __restrict__ Wl1,
    float* __restrict__ out)
{
    const int i = blockIdx.x;
    const int tid = threadIdx.x;
    float* f = g_feats + (size_t)i*960;

    if (tid < 96) {
        int hp = tid;
        const float* op = g_opt + (i*96 + hp)*3;
        float x = op[0] - trans[i*3+0];
        float y = op[1] - trans[i*3+1];
        float z = op[2] - trans[i*3+2];
        const float* R = rot + i*9;
        float lx = R[0]*x + R[3]*y + R[6]*z;
        float ly = R[1]*x + R[4]*y + R[7]*z;
        float lz = R[2]*x + R[5]*y + R[8]*z;
        f[192 + hp] = lx;
        f[288 + hp] = ly;
        f[384 + hp] = lz;
        f[480 + hp] = sqrtf(lx*lx + ly*ly + lz*lz + 1e-8f);
    }
    if (tid >= 96 && tid < 108) {
        int oc = tid - 96;
        int o = oc / 3, c = oc % 3;
        float acc = 0.f;
        #pragma unroll 8
        for (int hp = 0; hp < 96; hp++)
            acc += g_opt[(i*96 + hp)*3 + c] * Wl1[hp*4 + o];
        out[NN*CS + i*12 + oc] = l1_feats[i*12 + oc] + acc * 0.10206207261596575f;
    }
    for (int l = tid; l < 192; l += 128) f[l] = g_o[i*HC + l];
    for (int l = tid; l < 384; l += 128) f[576 + l] = g_opair[i*384 + l];
}

/* ---------------- K5b: output GEMM (tiled) ---------------- */
#define BI 32
#define BO 64
#define BK 16
#define FPAD (BI+2)   /* even stride -> float2-safe */
#define WPAD (BO+4)   /* multiple of 4 -> float4-safe */
__global__ __launch_bounds__(256) void k5b_gemm(
    const float* __restrict__ s, const float* __restrict__ Wout,
    const float* __restrict__ bout, float* __restrict__ out)
{
    __shared__ float ftT[BK][FPAD];   /* [k][i] */
    __shared__ float wtT[BK][WPAD];   /* [k][o] */
    const int o0 = blockIdx.x * BO;
    const int i0 = blockIdx.y * BI;
    const int tid = threadIdx.x;
    const int tx = tid & 15;          /* o group: 4 each */
    const int ty = tid >> 4;          /* i group: 2 each */

    float acc[2][4];
    #pragma unroll
    for (int r = 0; r < 2; r++)
        #pragma unroll
        for (int q = 0; q < 4; q++) acc[r][q] = 0.f;

    for (int k0 = 0; k0 < 960; k0 += BK) {
        for (int l = tid; l < BI*BK; l += 256) {
            int r = l / BK, c = l % BK;
            ftT[c][r] = g_feats[(size_t)(i0+r)*960 + k0 + c];
        }
        for (int l = tid; l < BO*BK; l += 256) {
            int r = l / BK, c = l % BK;
            wtT[c][r] = Wout[(size_t)(o0+r)*960 + k0 + c];
        }
        __syncthreads();
        #pragma unroll
        for (int kk = 0; kk < BK; kk++) {
            float2 fv = *(const float2*)&ftT[kk][ty*2];
            float4 wv = *(const float4*)&wtT[kk][tx*4];
            acc[0][0] += fv.x*wv.x; acc[0][1] += fv.x*wv.y;
            acc[0][2] += fv.x*wv.z; acc[0][3] += fv.x*wv.w;
            acc[1][0] += fv.y*wv.x; acc[1][1] += fv.y*wv.y;
            acc[1][2] += fv.y*wv.z; acc[1][3] += fv.y*wv.w;
        }
        __syncthreads();
    }
    #pragma unroll
    for (int r = 0; r < 2; r++) {
        int i = i0 + ty*2 + r;
        #pragma unroll
        for (int q = 0; q < 4; q++) {
            int o = o0 + tx*4 + q;
            out[(size_t)i*CS + o] = acc[r][q] + bout[o] + s[(size_t)i*CS + o];
        }
    }
}

/* ---------------- launcher ---------------- */
extern "C" void kernel_launch(void* const* d_in, const int* in_sizes, int n_in,
                              void* d_out, int out_size)
{
    const float* s      = (const float*)d_in[0];
    const float* z      = (const float*)d_in[1];
    const float* l1f    = (const float*)d_in[2];
    const float* rot    = (const float*)d_in[3];
    const float* trans  = (const float*)d_in[4];
    const float* mask   = (const float*)d_in[5];
    const float* Wq     = (const float*)d_in[6];
    const float* bq     = (const float*)d_in[7];
    const float* Wkv    = (const float*)d_in[8];
    const float* bkv    = (const float*)d_in[9];
    const float* Wqp    = (const float*)d_in[10];
    const float* bqp    = (const float*)d_in[11];
    const float* Wkvp   = (const float*)d_in[12];
    const float* bkvp   = (const float*)d_in[13];
    const float* Wb     = (const float*)d_in[14];
    const float* bb     = (const float*)d_in[15];
    const float* Wdz    = (const float*)d_in[16];
    const float* bdz    = (const float*)d_in[17];
    const float* Wout   = (const float*)d_in[18];
    const float* bout   = (const float*)d_in[19];
    const float* Wl1    = (const float*)d_in[20];
    float* out = (float*)d_out;

    cudaFuncSetAttribute(k1_proj, cudaFuncAttributeMaxDynamicSharedMemorySize, K1_SMEM);
    cudaFuncSetAttribute(k2_zproj, cudaFuncAttributeMaxDynamicSharedMemorySize, K2_SMEM);

    k1_proj<<<NN/K1_IT, 256, K1_SMEM>>>(s, rot, trans, Wq, bq, Wkv, bkv, Wqp, bqp, Wkvp, bkvp);
    k2_zproj<<<dim3(NN/JT, NN), 128, K2_SMEM>>>(z, Wb, bb, Wdz, bdz);
    k3_softmax<<<dim3(NN/2, HH), 256>>>(mask);
    k4_out<<<NN, 256>>>();
    k5a_feats<<<NN, 128>>>(l1f, rot, trans, Wl1, out);
    k5b_gemm<<<dim3(CS/BO, NN/BI), 256>>>(s, Wout, bout, out);
}

// round 16
// speedup vs baseline: 1.4291x; 1.4291x over previous
#include <cuda_runtime.h>
#include <math.h>

#define NN 768
#define CS 384
#define CZ 128
#define CH 16
#define HH 12
#define PQ 4
#define PV 8
#define HC (HH*CH)          /* 192 */
#define RAW_TOT 1152        /* 192 q + 384 kv + 144 qp + 432 kvp */

typedef unsigned long long u64;

__device__ __forceinline__ u64 pk2(float x, float y){
    u64 r; asm("mov.b64 %0, {%1,%2};" : "=l"(r) : "f"(x), "f"(y)); return r;
}
__device__ __forceinline__ void fma2(u64 &d, u64 a, u64 b){
    asm("fma.rn.f32x2 %0, %1, %2, %0;" : "+l"(d) : "l"(a), "l"(b));
}
__device__ __forceinline__ void upk2(float &x, float &y, u64 v){
    asm("mov.b64 {%0,%1}, %2;" : "=f"(x), "=f"(y) : "l"(v));
}

/* ---------------- scratch (device globals, no allocs) ---------------- */
__device__ float g_q   [NN*HC];
__device__ float g_kT  [(HH*28)*NN];        /* [h*28+u][j] */
__device__ float g_vT  [(HH*40)*NN];        /* [h*40+u][j] */
__device__ float g_qpts[NN*48*3];
__device__ float g_A   [(size_t)HH*NN*NN];  /* attn, [h][i][j] */
__device__ float g_pzT [(size_t)NN*32*NN];  /* [i][d][j] */
__device__ float g_o   [NN*HC];
__device__ float g_opt [NN*96*3];
__device__ float g_opair[NN*HH*32];
__device__ float g_feats[(size_t)NN*960];

/* ---------------- K1: input projections (8 residues per block) ---------------- */
#define K1_IT 8
#define K1_SMEM ((K1_IT*CS + K1_IT*RAW_TOT)*4)

__global__ __launch_bounds__(256) void k1_proj(
    const float* __restrict__ s, const float* __restrict__ rot, const float* __restrict__ trans,
    const float* __restrict__ Wq, const float* __restrict__ bq,
    const float* __restrict__ Wkv, const float* __restrict__ bkv,
    const float* __restrict__ Wqp, const float* __restrict__ bqp,
    const float* __restrict__ Wkvp, const float* __restrict__ bkvp)
{
    extern __shared__ float sm1[];
    float* s_s = sm1;
    float* raw = sm1 + K1_IT*CS;
    const int i0 = blockIdx.x * K1_IT;
    const int tid = threadIdx.x;

    for (int l = tid; l < K1_IT*CS; l += 256) {
        int ii = l / CS, c = l % CS;
        s_s[ii*CS + c] = s[(size_t)(i0+ii)*CS + c];
    }
    __syncthreads();

    const int w = tid >> 5, lane = tid & 31;
    for (int o = w; o < RAW_TOT; o += 8) {
        const float* wrow; float bias;
        if (o < 192)      { wrow = Wq   + (size_t)o*CS;        bias = bq[o]; }
        else if (o < 576) { wrow = Wkv  + (size_t)(o-192)*CS;  bias = bkv[o-192]; }
        else if (o < 720) { wrow = Wqp  + (size_t)(o-576)*CS;  bias = bqp[o-576]; }
        else              { wrow = Wkvp + (size_t)(o-720)*CS;  bias = bkvp[o-720]; }
        const float4* wr4 = (const float4*)wrow;
        float acc[K1_IT];
        #pragma unroll
        for (int ii = 0; ii < K1_IT; ii++) acc[ii] = 0.f;
        for (int cc = lane; cc < CS/4; cc += 32) {
            float4 wv = wr4[cc];
            #pragma unroll
            for (int ii = 0; ii < K1_IT; ii++) {
                float4 sv = *(const float4*)(s_s + ii*CS + cc*4);
                acc[ii] += sv.x*wv.x + sv.y*wv.y + sv.z*wv.z + sv.w*wv.w;
            }
        }
        #pragma unroll
        for (int ii = 0; ii < K1_IT; ii++) {
            float v = acc[ii];
            #pragma unroll
            for (int off = 16; off > 0; off >>= 1) v += __shfl_xor_sync(~0u, v, off);
            if (lane == 0) raw[ii*RAW_TOT + o] = v + bias;
        }
    }
    __syncthreads();

    for (int l = tid; l < K1_IT*768; l += 256) {
        int ii = l / 768, u = l % 768;
        int i = i0 + ii;
        const float* rw = raw + ii*RAW_TOT;
        if (u < 192) {
            g_q[i*HC + u] = rw[u];
        } else if (u < 576) {
            int o = u - 192; int h = o >> 5; int cc = o & 31;
            float v = rw[192 + o];
            if (cc < 16) g_kT[(size_t)(h*28 + cc)*NN + i] = v;
            else         g_vT[(size_t)(h*40 + (cc-16))*NN + i] = v;
        } else {
            float R0=rot[i*9+0],R1=rot[i*9+1],R2=rot[i*9+2],
                  R3=rot[i*9+3],R4=rot[i*9+4],R5=rot[i*9+5],
                  R6=rot[i*9+6],R7=rot[i*9+7],R8=rot[i*9+8];
            float T0=trans[i*3+0],T1=trans[i*3+1],T2=trans[i*3+2];
            if (u < 624) {
                int p = u - 576;
                float x = rw[576+p], y = rw[576+48+p], z = rw[576+96+p];
                float ox = R0*x + R1*y + R2*z + T0;
                float oy = R3*x + R4*y + R5*z + T1;
                float oz = R6*x + R7*y + R8*z + T2;
                int base = (i*48 + p)*3;
                g_qpts[base+0] = ox; g_qpts[base+1] = oy; g_qpts[base+2] = oz;
            } else {
                int p = u - 624;
                float x = rw[720+p], y = rw[720+144+p], z = rw[720+288+p];
                float ox = R0*x + R1*y + R2*z + T0;
                float oy = R3*x + R4*y + R5*z + T1;
                float oz = R6*x + R7*y + R8*z + T2;
                int h = p / 12, t2 = p % 12;
                if (t2 < 4) {
                    size_t b = (size_t)(h*28 + 16 + t2*3)*NN + i;
                    g_kT[b] = ox; g_kT[b+NN] = oy; g_kT[b+2*NN] = oz;
                } else {
                    int pp = t2 - 4;
                    size_t b = (size_t)(h*40 + 16 + pp*3)*NN + i;
                    g_vT[b] = ox; g_vT[b+NN] = oy; g_vT[b+2*NN] = oz;
                }
            }
        }
    }
}

/* ---------------- K2: z projection with packed f32x2 FMA ---------------- */
#define JT 128
#define ZPAD 132
#define K2_SMEM ((JT*ZPAD + 128*48)*4)

__global__ __launch_bounds__(128) void k2_zproj(
    const float* __restrict__ z, const float* __restrict__ Wb, const float* __restrict__ bb,
    const float* __restrict__ Wdz, const float* __restrict__ bdz)
{
    extern __shared__ float sm2[];
    float* zs  = sm2;
    float* wst = sm2 + JT*ZPAD;
    const int i = blockIdx.y;
    const int jbase = blockIdx.x * JT;
    const int tid = threadIdx.x;

    for (int l = tid; l < 48*CZ; l += 128) {
        int o = l >> 7, c = l & 127;
        float v = 0.f;
        if (o < 12)      v = Wb[o*CZ + c];
        else if (o < 44) v = Wdz[(o-12)*CZ + c];
        wst[c*48 + o] = v;
    }
    const float4* zg = (const float4*)(z + ((size_t)i*NN + jbase)*CZ);
    for (int l4 = tid; l4 < JT*CZ/4; l4 += 128) {
        float4 v = zg[l4];
        int r = l4 >> 5, c4 = l4 & 31;
        *(float4*)(zs + r*ZPAD + c4*4) = v;
    }
    __syncthreads();

    const int jg = tid & 15;
    const int og = tid >> 4;
    u64 acc[8][3];
    #pragma unroll
    for (int m = 0; m < 8; m++) { acc[m][0]=0ull; acc[m][1]=0ull; acc[m][2]=0ull; }

    for (int c4 = 0; c4 < CZ/4; c4++) {
        float4 zr[8];
        #pragma unroll
        for (int m = 0; m < 8; m++)
            zr[m] = *(const float4*)(zs + (jg + 16*m)*ZPAD + c4*4);
        #pragma unroll
        for (int cc = 0; cc < 4; cc++) {
            const float* wrow = wst + (c4*4+cc)*48 + og*6;
            u64 w0 = *(const u64*)(wrow);
            u64 w1 = *(const u64*)(wrow + 2);
            u64 w2 = *(const u64*)(wrow + 4);
            #pragma unroll
            for (int m = 0; m < 8; m++) {
                float zv = (cc==0) ? zr[m].x : (cc==1) ? zr[m].y : (cc==2) ? zr[m].z : zr[m].w;
                u64 zz = pk2(zv, zv);
                fma2(acc[m][0], zz, w0);
                fma2(acc[m][1], zz, w1);
                fma2(acc[m][2], zz, w2);
            }
        }
    }

    float bs[6];
    #pragma unroll
    for (int oo = 0; oo < 6; oo++) {
        int o = og*6 + oo;
        bs[oo] = (o < 12) ? bb[o] : (o < 44) ? bdz[o-12] : 0.f;
    }
    #pragma unroll
    for (int m = 0; m < 8; m++) {
        float av[6];
        upk2(av[0], av[1], acc[m][0]);
        upk2(av[2], av[3], acc[m][1]);
        upk2(av[4], av[5], acc[m][2]);
        int j = jbase + jg + 16*m;
        #pragma unroll
        for (int oo = 0; oo < 6; oo++) {
            int o = og*6 + oo;
            float v = av[oo] + bs[oo];
            if (o < 12)      g_A[((size_t)o*NN + i)*NN + j] = v;
            else if (o < 44) g_pzT[((size_t)i*32 + (o-12))*NN + j] = v;
        }
    }
}

/* ---------------- K3: logits + softmax ---------------- */
__global__ __launch_bounds__(256) void k3_softmax(const float* __restrict__ mask)
{
    const int i0 = blockIdx.x * 2, h = blockIdx.y;
    __shared__ float l_s[2][NN];
    __shared__ float q_s[2][16];
    __shared__ float qp_s[2][12];
    __shared__ float red[8];
    const int tid = threadIdx.x;
    if (tid < 32) q_s[tid>>4][tid&15] = g_q[(i0 + (tid>>4))*HC + h*16 + (tid&15)];
    if (tid >= 32 && tid < 56) {
        int idx = tid - 32; int r = idx / 12, u = idx % 12;
        qp_s[r][u] = g_qpts[((i0+r)*48 + h*4)*3 + u];
    }
    __syncthreads();

    const float m0 = mask[i0], m1 = mask[i0+1];
    const float c1 = 0.14433756729740643f;
    const float c2 = 0.5773502691896258f;
    const float* kTb = g_kT + (size_t)h*28*NN;
    float lmax0 = -1e30f, lmax1 = -1e30f;
    for (int j = tid; j < NN; j += 256) {
        float kv[28];
        #pragma unroll
        for (int u = 0; u < 28; u++) kv[u] = kTb[(size_t)u*NN + j];
        float mj = mask[j];
        float b0 = g_A[((size_t)h*NN + i0  )*NN + j];
        float b1 = g_A[((size_t)h*NN + i0+1)*NN + j];
        float qk0 = 0.f, qk1 = 0.f;
        #pragma unroll
        for (int c = 0; c < 16; c++) { qk0 += q_s[0][c]*kv[c]; qk1 += q_s[1][c]*kv[c]; }
        float pt0 = 0.f, pt1 = 0.f;
        #pragma unroll
        for (int u = 0; u < 12; u++) {
            float d0 = qp_s[0][u] - kv[16+u]; pt0 += d0*d0;
            float d1 = qp_s[1][u] - kv[16+u]; pt1 += d1*d1;
        }
        float lg0 = c1*qk0 + c2*b0 - 0.5f*pt0 + 100000.0f*(m0*mj - 1.0f);
        float lg1 = c1*qk1 + c2*b1 - 0.5f*pt1 + 100000.0f*(m1*mj - 1.0f);
        l_s[0][j] = lg0; l_s[1][j] = lg1;
        lmax0 = fmaxf(lmax0, lg0); lmax1 = fmaxf(lmax1, lg1);
    }

    #pragma unroll
    for (int r = 0; r < 2; r++) {
        float lmax = r ? lmax1 : lmax0;
        #pragma unroll
        for (int o = 16; o > 0; o >>= 1) lmax = fmaxf(lmax, __shfl_xor_sync(~0u, lmax, o));
        if ((tid & 31) == 0) red[tid>>5] = lmax;
        __syncthreads();
        if (tid < 32) {
            float v = (tid < 8) ? red[tid] : -1e30f;
            #pragma unroll
            for (int o = 4; o > 0; o >>= 1) v = fmaxf(v, __shfl_xor_sync(~0u, v, o));
            if (tid == 0) red[0] = v;
        }
        __syncthreads();
        lmax = red[0];
        __syncthreads();

        float lsum = 0.f;
        for (int j = tid; j < NN; j += 256) {
            float e = __expf(l_s[r][j] - lmax);
            l_s[r][j] = e;
            lsum += e;
        }
        #pragma unroll
        for (int o = 16; o > 0; o >>= 1) lsum += __shfl_xor_sync(~0u, lsum, o);
        if ((tid & 31) == 0) red[tid>>5] = lsum;
        __syncthreads();
        if (tid < 32) {
            float v = (tid < 8) ? red[tid] : 0.f;
            #pragma unroll
            for (int o = 4; o > 0; o >>= 1) v += __shfl_xor_sync(~0u, v, o);
            if (tid == 0) red[0] = v;
        }
        __syncthreads();
        float inv = 1.0f / red[0];
        float* arow = g_A + ((size_t)h*NN + i0 + r)*NN;
        for (int j = tid; j < NN; j += 256) arow[j] = l_s[r][j]*inv;
        __syncthreads();
    }
}

/* ---------------- K4a: o + o_pt, i-tiled (8 residues x 1 head per CTA) -------- */
#define K4A_IT 8
__global__ __launch_bounds__(256) void k4a_ov(void)
{
    const int i0 = blockIdx.x * K4A_IT;
    const int h  = blockIdx.y;
    __shared__ float a_s[K4A_IT][NN];     /* 24 KB */
    const int tid = threadIdx.x;
    for (int l = tid; l < K4A_IT*(NN/4); l += 256) {
        int ii = l / (NN/4), j4 = l % (NN/4);
        ((float4*)a_s[ii])[j4] =
            ((const float4*)(g_A + ((size_t)h*NN + i0 + ii)*NN))[j4];
    }
    __syncthreads();
    const int w = tid >> 5, lane = tid & 31;   /* warp w handles u = w*5 .. w*5+4 */

    float acc[5][K4A_IT];
    #pragma unroll
    for (int uu = 0; uu < 5; uu++)
        #pragma unroll
        for (int ii = 0; ii < K4A_IT; ii++) acc[uu][ii] = 0.f;

    const size_t vbase = (size_t)(h*40 + w*5)*NN;
    #pragma unroll
    for (int jc = 0; jc < 6; jc++) {
        int idx = jc*32 + lane;
        float4 a[K4A_IT];
        #pragma unroll
        for (int ii = 0; ii < K4A_IT; ii++) a[ii] = ((const float4*)a_s[ii])[idx];
        #pragma unroll
        for (int uu = 0; uu < 5; uu++) {
            float4 v = ((const float4*)(g_vT + vbase + (size_t)uu*NN))[idx];
            #pragma unroll
            for (int ii = 0; ii < K4A_IT; ii++)
                acc[uu][ii] += a[ii].x*v.x + a[ii].y*v.y + a[ii].z*v.z + a[ii].w*v.w;
        }
    }
    #pragma unroll
    for (int uu = 0; uu < 5; uu++)
        #pragma unroll
        for (int ii = 0; ii < K4A_IT; ii++) {
            float s = acc[uu][ii];
            #pragma unroll
            for (int o = 16; o > 0; o >>= 1) s += __shfl_xor_sync(~0u, s, o);
            acc[uu][ii] = s;
        }
    if (lane == 0) {
        #pragma unroll
        for (int uu = 0; uu < 5; uu++) {
            int u = w*5 + uu;
            #pragma unroll
            for (int ii = 0; ii < K4A_IT; ii++) {
                int i = i0 + ii;
                if (u < 16) g_o[i*HC + h*16 + u] = acc[uu][ii];
                else { int pp = u - 16; g_opt[(i*96 + h*8 + pp/3)*3 + pp%3] = acc[uu][ii]; }
            }
        }
    }
}

/* ---------------- K4b: o_pair per residue ---------------- */
__global__ __launch_bounds__(256, 3) void k4b_opair(void)
{
    const int i = blockIdx.x;
    __shared__ float a_s[HH][NN];          /* 36 KB */
    const int tid = threadIdx.x;
    for (int l = tid; l < HH*(NN/4); l += 256) {
        int h = l / (NN/4), j4 = l % (NN/4);
        ((float4*)a_s[h])[j4] = ((const float4*)(g_A + ((size_t)h*NN + i)*NN))[j4];
    }
    __syncthreads();
    const int w = tid >> 5, lane = tid & 31;

    for (int p = 0; p < 2; p++) {
        int d0 = w*4 + p*2;
        const float4* p0 = (const float4*)(g_pzT + ((size_t)i*32 + d0    )*NN);
        const float4* p1 = (const float4*)(g_pzT + ((size_t)i*32 + d0 + 1)*NN);
        float acc0[HH], acc1[HH];
        #pragma unroll
        for (int h = 0; h < HH; h++) { acc0[h] = 0.f; acc1[h] = 0.f; }
        #pragma unroll
        for (int jc = 0; jc < 6; jc++) {
            int idx = jc*32 + lane;
            float4 q0 = p0[idx], q1 = p1[idx];
            #pragma unroll
            for (int h = 0; h < HH; h++) {
                float4 av = ((const float4*)a_s[h])[idx];
                acc0[h] += av.x*q0.x + av.y*q0.y + av.z*q0.z + av.w*q0.w;
                acc1[h] += av.x*q1.x + av.y*q1.y + av.z*q1.z + av.w*q1.w;
            }
        }
        #pragma unroll
        for (int h = 0; h < HH; h++) {
            float v0 = acc0[h], v1 = acc1[h];
            #pragma unroll
            for (int o = 16; o > 0; o >>= 1) {
                v0 += __shfl_xor_sync(~0u, v0, o);
                v1 += __shfl_xor_sync(~0u, v1, o);
            }
            if (lane == 0) {
                g_opair[(i*HH + h)*32 + d0    ] = v0;
                g_opair[(i*HH + h)*32 + d0 + 1] = v1;
            }
        }
    }
}

/* ---------------- K5a: feats assembly + l1 out ---------------- */
__global__ __launch_bounds__(128) void k5a_feats(
    const float* __restrict__ l1_feats, const float* __restrict__ rot,
    const float* __restrict__ trans, const float* __restrict__ Wl1,
    float* __restrict__ out)
{
    const int i = blockIdx.x;
    const int tid = threadIdx.x;
    float* f = g_feats + (size_t)i*960;

    if (tid < 96) {
        int hp = tid;
        const float* op = g_opt + (i*96 + hp)*3;
        float x = op[0] - trans[i*3+0];
        float y = op[1] - trans[i*3+1];
        float z = op[2] - trans[i*3+2];
        const float* R = rot + i*9;
        float lx = R[0]*x + R[3]*y + R[6]*z;
        float ly = R[1]*x + R[4]*y + R[7]*z;
        float lz = R[2]*x + R[5]*y + R[8]*z;
        f[192 + hp] = lx;
        f[288 + hp] = ly;
        f[384 + hp] = lz;
        f[480 + hp] = sqrtf(lx*lx + ly*ly + lz*lz + 1e-8f);
    }
    if (tid >= 96 && tid < 108) {
        int oc = tid - 96;
        int o = oc / 3, c = oc % 3;
        float acc = 0.f;
        #pragma unroll 8
        for (int hp = 0; hp < 96; hp++)
            acc += g_opt[(i*96 + hp)*3 + c] * Wl1[hp*4 + o];
        out[NN*CS + i*12 + oc] = l1_feats[i*12 + oc] + acc * 0.10206207261596575f;
    }
    for (int l = tid; l < 192; l += 128) f[l] = g_o[i*HC + l];
    for (int l = tid; l < 384; l += 128) f[576 + l] = g_opair[i*384 + l];
}

/* ---------------- K5b: output GEMM (tiled) ---------------- */
#define BI 32
#define BO 64
#define BK 16
#define FPAD (BI+2)
#define WPAD (BO+4)
__global__ __launch_bounds__(256) void k5b_gemm(
    const float* __restrict__ s, const float* __restrict__ Wout,
    const float* __restrict__ bout, float* __restrict__ out)
{
    __shared__ float ftT[BK][FPAD];
    __shared__ float wtT[BK][WPAD];
    const int o0 = blockIdx.x * BO;
    const int i0 = blockIdx.y * BI;
    const int tid = threadIdx.x;
    const int tx = tid & 15;
    const int ty = tid >> 4;

    float acc[2][4];
    #pragma unroll
    for (int r = 0; r < 2; r++)
        #pragma unroll
        for (int q = 0; q < 4; q++) acc[r][q] = 0.f;

    for (int k0 = 0; k0 < 960; k0 += BK) {
        for (int l = tid; l < BI*BK; l += 256) {
            int r = l / BK, c = l % BK;
            ftT[c][r] = g_feats[(size_t)(i0+r)*960 + k0 + c];
        }
        for (int l = tid; l < BO*BK; l += 256) {
            int r = l / BK, c = l % BK;
            wtT[c][r] = Wout[(size_t)(o0+r)*960 + k0 + c];
        }
        __syncthreads();
        #pragma unroll
        for (int kk = 0; kk < BK; kk++) {
            float2 fv = *(const float2*)&ftT[kk][ty*2];
            float4 wv = *(const float4*)&wtT[kk][tx*4];
            acc[0][0] += fv.x*wv.x; acc[0][1] += fv.x*wv.y;
            acc[0][2] += fv.x*wv.z; acc[0][3] += fv.x*wv.w;
            acc[1][0] += fv.y*wv.x; acc[1][1] += fv.y*wv.y;
            acc[1][2] += fv.y*wv.z; acc[1][3] += fv.y*wv.w;
        }
        __syncthreads();
    }
    #pragma unroll
    for (int r = 0; r < 2; r++) {
        int i = i0 + ty*2 + r;
        #pragma unroll
        for (int q = 0; q < 4; q++) {
            int o = o0 + tx*4 + q;
            out[(size_t)i*CS + o] = acc[r][q] + bout[o] + s[(size_t)i*CS + o];
        }
    }
}

/* ---------------- launcher ---------------- */
extern "C" void kernel_launch(void* const* d_in, const int* in_sizes, int n_in,
                              void* d_out, int out_size)
{
    const float* s      = (const float*)d_in[0];
    const float* z      = (const float*)d_in[1];
    const float* l1f    = (const float*)d_in[2];
    const float* rot    = (const float*)d_in[3];
    const float* trans  = (const float*)d_in[4];
    const float* mask   = (const float*)d_in[5];
    const float* Wq     = (const float*)d_in[6];
    const float* bq     = (const float*)d_in[7];
    const float* Wkv    = (const float*)d_in[8];
    const float* bkv    = (const float*)d_in[9];
    const float* Wqp    = (const float*)d_in[10];
    const float* bqp    = (const float*)d_in[11];
    const float* Wkvp   = (const float*)d_in[12];
    const float* bkvp   = (const float*)d_in[13];
    const float* Wb     = (const float*)d_in[14];
    const float* bb     = (const float*)d_in[15];
    const float* Wdz    = (const float*)d_in[16];
    const float* bdz    = (const float*)d_in[17];
    const float* Wout   = (const float*)d_in[18];
    const float* bout   = (const float*)d_in[19];
    const float* Wl1    = (const float*)d_in[20];
    float* out = (float*)d_out;

    cudaFuncSetAttribute(k1_proj, cudaFuncAttributeMaxDynamicSharedMemorySize, K1_SMEM);
    cudaFuncSetAttribute(k2_zproj, cudaFuncAttributeMaxDynamicSharedMemorySize, K2_SMEM);

    k1_proj<<<NN/K1_IT, 256, K1_SMEM>>>(s, rot, trans, Wq, bq, Wkv, bkv, Wqp, bqp, Wkvp, bkvp);
    k2_zproj<<<dim3(NN/JT, NN), 128, K2_SMEM>>>(z, Wb, bb, Wdz, bdz);
    k3_softmax<<<dim3(NN/2, HH), 256>>>(mask);
    k4a_ov<<<dim3(NN/K4A_IT, HH), 256>>>();
    k4b_opair<<<NN, 256>>>();
    k5a_feats<<<NN, 128>>>(l1f, rot, trans, Wl1, out);
    k5b_gemm<<<dim3(CS/BO, NN/BI), 256>>>(s, Wout, bout, out);
}